// round 9
// baseline (speedup 1.0000x reference)
#include <cuda_runtime.h>
#include <cuda_fp16.h>
#include <cstdint>

#define NN 50000
#define NE 800000
#define D 128
#define DOUT 64
#define SCAN_B 512
#define NBLK ((NN + SCAN_B - 1) / SCAN_B)   // 98
#define NH0 25088                            // first half rows (196 * 128)

// ---- scratch (__device__ globals: allocation-free rule) ----
__device__ int    g_cnt[NN];
__device__ int    g_fill[NN];
__device__ int    g_rowptr[NN + 1];
__device__ float  g_dinv[NN];
__device__ int    g_blksum[NBLK];
__device__ int    g_ecol[NE];
__device__ __half g_t0[NN * D];        // message buffers (dinv-scaled hW, fp16)
__device__ __half g_t1[NN * D];
__device__ __half g_h[NN * D];         // layer features (fp16)
__device__ float  g_wt_hi[3][D * D];
__device__ float  g_wt_lo[3][D * D];
__device__ float  g_wfc_hi[DOUT * D];
__device__ float  g_wfc_lo[DOUT * D];

// ================= helpers =================
__device__ __forceinline__ float tf32rn(float x) {
    uint32_t r;
    asm("cvt.rna.tf32.f32 %0, %1;" : "=r"(r) : "f"(x));
    return __uint_as_float(r);
}
__device__ __forceinline__ void split_tf32(float x, uint32_t& hi, uint32_t& lo) {
    asm("cvt.rna.tf32.f32 %0, %1;" : "=r"(hi) : "f"(x));
    float r = x - __uint_as_float(hi);
    asm("cvt.rna.tf32.f32 %0, %1;" : "=r"(lo) : "f"(r));
}
__device__ __forceinline__ void mma_tf32(float* c, const uint32_t* a, const uint32_t* b) {
    asm volatile(
        "mma.sync.aligned.m16n8k8.row.col.f32.tf32.tf32.f32 "
        "{%0,%1,%2,%3}, {%4,%5,%6,%7}, {%8,%9}, {%0,%1,%2,%3};"
        : "+f"(c[0]), "+f"(c[1]), "+f"(c[2]), "+f"(c[3])
        : "r"(a[0]), "r"(a[1]), "r"(a[2]), "r"(a[3]), "r"(b[0]), "r"(b[1]));
}

// ================= CSR build =================
__global__ void count_kernel(const int* __restrict__ dst) {
    int e = blockIdx.x * blockDim.x + threadIdx.x;
    if (e < NE) atomicAdd(&g_cnt[dst[e]], 1);
}

__global__ void scan1_kernel() {
    __shared__ int wsum[16];
    int t = threadIdx.x;
    int i = blockIdx.x * SCAN_B + t;
    int v = (i < NN) ? g_cnt[i] : 0;
    if (i < NN) g_dinv[i] = rsqrtf((float)v + 1.0f);
    int lane = t & 31, w = t >> 5;
    int s = v;
    #pragma unroll
    for (int off = 1; off < 32; off <<= 1) {
        int x = __shfl_up_sync(0xFFFFFFFF, s, off);
        if (lane >= off) s += x;
    }
    if (lane == 31) wsum[w] = s;
    __syncthreads();
    if (w == 0) {
        int ws = (lane < 16) ? wsum[lane] : 0;
        #pragma unroll
        for (int off = 1; off < 16; off <<= 1) {
            int x = __shfl_up_sync(0xFFFFFFFF, ws, off);
            if (lane >= off) ws += x;
        }
        if (lane < 16) wsum[lane] = ws;
    }
    __syncthreads();
    if (w > 0) s += wsum[w - 1];
    if (i < NN) g_rowptr[i + 1] = s;
    if (t == SCAN_B - 1) g_blksum[blockIdx.x] = s;
}

__global__ void scan23_kernel() {
    __shared__ int s[128];
    int t = threadIdx.x;
    if (t < 128) s[t] = (t < NBLK) ? g_blksum[t] : 0;
    __syncthreads();
    #pragma unroll
    for (int off = 1; off < 128; off <<= 1) {
        int x = (t >= off && t < 128) ? s[t - off] : 0;
        __syncthreads();
        if (t < 128) s[t] += x;
        __syncthreads();
    }
    int i = blockIdx.x * 256 + t;
    if (i < NN) {
        int blk = i / SCAN_B;
        int off = (blk > 0) ? s[blk - 1] : 0;
        g_rowptr[i + 1] += off;
        g_fill[i] = 0;
    }
    if (i == 0) g_rowptr[0] = 0;
}

__global__ void fill_kernel(const int* __restrict__ src,
                            const int* __restrict__ dst) {
    int e = blockIdx.x * blockDim.x + threadIdx.x;
    if (e >= NE) return;
    int d = dst[e];
    int pos = g_rowptr[d] + atomicAdd(&g_fill[d], 1);
    g_ecol[pos] = src[e];
}

// ===== all-weight transpose + tf32 hi/lo split =====
__global__ void wsplit_all_kernel(const float* __restrict__ W1,
                                  const float* __restrict__ W2,
                                  const float* __restrict__ W3,
                                  const float* __restrict__ Wfc) {
    int idx = blockIdx.x * blockDim.x + threadIdx.x;
    const int SQ = D * D;
    const float* W;
    float *hi, *lo;
    int ncols, local;
    if (idx < SQ)          { W = W1;  hi = g_wt_hi[0]; lo = g_wt_lo[0]; ncols = D;    local = idx; }
    else if (idx < 2 * SQ) { W = W2;  hi = g_wt_hi[1]; lo = g_wt_lo[1]; ncols = D;    local = idx - SQ; }
    else if (idx < 3 * SQ) { W = W3;  hi = g_wt_hi[2]; lo = g_wt_lo[2]; ncols = D;    local = idx - 2 * SQ; }
    else if (idx < 3 * SQ + DOUT * D)
                           { W = Wfc; hi = g_wfc_hi;   lo = g_wfc_lo;   ncols = DOUT; local = idx - 3 * SQ; }
    else return;
    int n = local / D, k = local % D;
    float w = W[k * ncols + n];
    float h_ = tf32rn(w);
    hi[local] = h_;
    lo[local] = tf32rn(w - h_);
}

// ===== mma.sync tf32 GEMM: C[M,BN] = A[M,128] @ (Bhi+Blo)^T, 3-term split =====
// AHALF: A rows are fp16.  EPI 0: half2 C[r,:] = acc*dinv[r]; EPI 1: float C = acc+bias.
template<int BN, int EPI, bool AHALF>
__global__ void __launch_bounds__(256, 1)
mma_gemm_kernel(const void* __restrict__ Ain,
                const float* __restrict__ Bhi,
                const float* __restrict__ Blo,
                const float* __restrict__ bias,
                const float* __restrict__ dinv,
                void* __restrict__ Cout, int M) {
    constexpr int TN_W = BN / 2;
    constexpr int NT = TN_W / 8;
    constexpr int LDS = 132;
    extern __shared__ float s[];
    float* As = s;
    float* Bh = s + 128 * LDS;
    float* Bl = Bh + BN * LDS;

    const int tid = threadIdx.x;
    const int lane = tid & 31, warp = tid >> 5;
    const int warpM = warp & 3, warpN = warp >> 2;
    const int rowBlk = blockIdx.x * 128;
    const int g = lane >> 2, tig = lane & 3;

    if (AHALF) {
        const __half* Ah = (const __half*)Ain;
        // 128 rows x 16 uint4/row = 2048 items = 8 iterations of 256 threads
        #pragma unroll
        for (int i = 0; i < 8; i++) {
            int idx = i * 256 + tid;
            int r = idx >> 4, c8 = idx & 15;   // 16 threads/row, 8 halves each
            float4 lo4 = make_float4(0.f, 0.f, 0.f, 0.f);
            float4 hi4 = make_float4(0.f, 0.f, 0.f, 0.f);
            if (rowBlk + r < M) {
                uint4 u = ((const uint4*)(Ah + (size_t)(rowBlk + r) * D))[c8];
                float2 f0 = __half22float2(*(__half2*)&u.x);
                float2 f1 = __half22float2(*(__half2*)&u.y);
                float2 f2 = __half22float2(*(__half2*)&u.z);
                float2 f3 = __half22float2(*(__half2*)&u.w);
                lo4 = make_float4(f0.x, f0.y, f1.x, f1.y);
                hi4 = make_float4(f2.x, f2.y, f3.x, f3.y);
            }
            *(float4*)(As + r * LDS + c8 * 8)     = lo4;
            *(float4*)(As + r * LDS + c8 * 8 + 4) = hi4;
        }
    } else {
        const float* Af = (const float*)Ain;
        #pragma unroll
        for (int i = 0; i < 16; i++) {
            int idx = i * 256 + tid;
            int r = idx >> 5, c4 = idx & 31;
            float4 v = make_float4(0.f, 0.f, 0.f, 0.f);
            if (rowBlk + r < M) v = ((const float4*)Af)[(size_t)(rowBlk + r) * 32 + c4];
            *(float4*)(As + r * LDS + c4 * 4) = v;
        }
    }
    #pragma unroll
    for (int i = 0; i < BN / 8; i++) {
        int idx = i * 256 + tid;
        int r = idx >> 5, c4 = idx & 31;
        *(float4*)(Bh + r * LDS + c4 * 4) = ((const float4*)Bhi)[(size_t)r * 32 + c4];
        *(float4*)(Bl + r * LDS + c4 * 4) = ((const float4*)Blo)[(size_t)r * 32 + c4];
    }
    __syncthreads();

    float acc[2][NT][4];
    #pragma unroll
    for (int mt = 0; mt < 2; mt++)
        #pragma unroll
        for (int nt = 0; nt < NT; nt++)
            #pragma unroll
            for (int q = 0; q < 4; q++) acc[mt][nt][q] = 0.f;

    const int aBase = warpM * 32;
    const int nBase = warpN * TN_W;

    #pragma unroll 4
    for (int ks = 0; ks < 16; ks++) {
        const int k0 = ks * 8;
        uint32_t ahi[2][4], alo[2][4];
        #pragma unroll
        for (int mt = 0; mt < 2; mt++) {
            int r0 = aBase + mt * 16 + g;
            float a0 = As[r0 * LDS + k0 + tig];
            float a1 = As[(r0 + 8) * LDS + k0 + tig];
            float a2 = As[r0 * LDS + k0 + tig + 4];
            float a3 = As[(r0 + 8) * LDS + k0 + tig + 4];
            split_tf32(a0, ahi[mt][0], alo[mt][0]);
            split_tf32(a1, ahi[mt][1], alo[mt][1]);
            split_tf32(a2, ahi[mt][2], alo[mt][2]);
            split_tf32(a3, ahi[mt][3], alo[mt][3]);
        }
        uint32_t bhi[NT][2], blo[NT][2];
        #pragma unroll
        for (int nt = 0; nt < NT; nt++) {
            int n = nBase + nt * 8 + g;
            bhi[nt][0] = __float_as_uint(Bh[n * LDS + k0 + tig]);
            bhi[nt][1] = __float_as_uint(Bh[n * LDS + k0 + tig + 4]);
            blo[nt][0] = __float_as_uint(Bl[n * LDS + k0 + tig]);
            blo[nt][1] = __float_as_uint(Bl[n * LDS + k0 + tig + 4]);
        }
        #pragma unroll
        for (int mt = 0; mt < 2; mt++)
            #pragma unroll
            for (int nt = 0; nt < NT; nt++)
                mma_tf32(acc[mt][nt], ahi[mt], bhi[nt]);
        #pragma unroll
        for (int mt = 0; mt < 2; mt++)
            #pragma unroll
            for (int nt = 0; nt < NT; nt++)
                mma_tf32(acc[mt][nt], alo[mt], bhi[nt]);
        #pragma unroll
        for (int mt = 0; mt < 2; mt++)
            #pragma unroll
            for (int nt = 0; nt < NT; nt++)
                mma_tf32(acc[mt][nt], ahi[mt], blo[nt]);
    }

    #pragma unroll
    for (int mt = 0; mt < 2; mt++) {
        int r0 = rowBlk + aBase + mt * 16 + g;
        int r1 = r0 + 8;
        float s0 = 1.f, s1 = 1.f;
        if (EPI == 0) {
            if (r0 < M) s0 = dinv[r0];
            if (r1 < M) s1 = dinv[r1];
        }
        #pragma unroll
        for (int nt = 0; nt < NT; nt++) {
            int cn = nBase + nt * 8 + 2 * tig;
            float2 v0 = make_float2(acc[mt][nt][0], acc[mt][nt][1]);
            float2 v1 = make_float2(acc[mt][nt][2], acc[mt][nt][3]);
            if (EPI == 0) {
                v0.x *= s0; v0.y *= s0; v1.x *= s1; v1.y *= s1;
                __half* Ch = (__half*)Cout;
                if (r0 < M) *(__half2*)(Ch + (size_t)r0 * BN + cn) = __float22half2_rn(v0);
                if (r1 < M) *(__half2*)(Ch + (size_t)r1 * BN + cn) = __float22half2_rn(v1);
            } else {
                float b0 = bias[cn], b1 = bias[cn + 1];
                v0.x += b0; v0.y += b1; v1.x += b0; v1.y += b1;
                float* Cf = (float*)Cout;
                if (r0 < M) *(float2*)(Cf + (size_t)r0 * BN + cn) = v0;
                if (r1 < M) *(float2*)(Cf + (size_t)r1 * BN + cn) = v1;
            }
        }
    }
}

// ========= gather: warp per node, fp16 in, fp16 out, fp32 accumulate, MLP=8 =========
__device__ __forceinline__ float4 ldrow_h(const uint2* __restrict__ t2, int row, int lane) {
    uint2 u = __ldg(t2 + (size_t)row * 32 + lane);
    float2 fa = __half22float2(*(__half2*)&u.x);
    float2 fb = __half22float2(*(__half2*)&u.y);
    return make_float4(fa.x, fa.y, fb.x, fb.y);
}

__global__ void gather_kernel(const __half* __restrict__ tin,
                              const float* __restrict__ bias,
                              __half* __restrict__ hout,
                              int nodeOff, int nodeEnd) {
    int node = nodeOff + ((blockIdx.x * blockDim.x + threadIdx.x) >> 5);
    int lane = threadIdx.x & 31;
    if (node >= nodeEnd) return;
    const uint2* t2 = (const uint2*)tin;

    float4 acc = ldrow_h(t2, node, lane);   // self term (pre-scaled)
    int e = g_rowptr[node], end = g_rowptr[node + 1];
    for (; e + 8 <= end; e += 8) {
        int sc[8];
        #pragma unroll
        for (int j = 0; j < 8; j++) sc[j] = g_ecol[e + j];
        float4 v[8];
        #pragma unroll
        for (int j = 0; j < 8; j++) v[j] = ldrow_h(t2, sc[j], lane);
        #pragma unroll
        for (int j = 0; j < 8; j++) {
            acc.x += v[j].x; acc.y += v[j].y; acc.z += v[j].z; acc.w += v[j].w;
        }
    }
    if (e + 4 <= end) {
        int sc[4];
        #pragma unroll
        for (int j = 0; j < 4; j++) sc[j] = g_ecol[e + j];
        float4 v[4];
        #pragma unroll
        for (int j = 0; j < 4; j++) v[j] = ldrow_h(t2, sc[j], lane);
        #pragma unroll
        for (int j = 0; j < 4; j++) {
            acc.x += v[j].x; acc.y += v[j].y; acc.z += v[j].z; acc.w += v[j].w;
        }
        e += 4;
    }
    for (; e < end; e++) {
        float4 v = ldrow_h(t2, g_ecol[e], lane);
        acc.x += v.x; acc.y += v.y; acc.z += v.z; acc.w += v.w;
    }
    float dd = g_dinv[node];
    float4 b = ((const float4*)bias)[lane];
    float2 p0 = make_float2(fmaxf(fmaf(dd, acc.x, b.x), 0.0f),
                            fmaxf(fmaf(dd, acc.y, b.y), 0.0f));
    float2 p1 = make_float2(fmaxf(fmaf(dd, acc.z, b.z), 0.0f),
                            fmaxf(fmaf(dd, acc.w, b.w), 0.0f));
    uint2 o;
    *(__half2*)&o.x = __float22half2_rn(p0);
    *(__half2*)&o.y = __float22half2_rn(p1);
    ((uint2*)hout)[(size_t)node * 32 + lane] = o;
}

// ================= launch =================
extern "C" void kernel_launch(void* const* d_in, const int* in_sizes, int n_in,
                              void* d_out, int out_size) {
    const float* x   = (const float*)d_in[0];
    const int* eidx  = (const int*)d_in[1];
    const float* W1  = (const float*)d_in[2];
    const float* b1  = (const float*)d_in[3];
    const float* W2  = (const float*)d_in[4];
    const float* b2  = (const float*)d_in[5];
    const float* W3  = (const float*)d_in[6];
    const float* b3  = (const float*)d_in[7];
    const float* Wfc = (const float*)d_in[8];
    const float* bfc = (const float*)d_in[9];
    float* out = (float*)d_out;

    const int* src = eidx;
    const int* dst = eidx + NE;

    __half* t0; cudaGetSymbolAddress((void**)&t0, g_t0);
    __half* t1; cudaGetSymbolAddress((void**)&t1, g_t1);
    __half* h;  cudaGetSymbolAddress((void**)&h, g_h);
    int* cnt;   cudaGetSymbolAddress((void**)&cnt, g_cnt);
    float* dinv; cudaGetSymbolAddress((void**)&dinv, g_dinv);
    float* whi; cudaGetSymbolAddress((void**)&whi, g_wt_hi);
    float* wlo; cudaGetSymbolAddress((void**)&wlo, g_wt_lo);
    float* fhi; cudaGetSymbolAddress((void**)&fhi, g_wfc_hi);
    float* flo; cudaGetSymbolAddress((void**)&flo, g_wfc_lo);

    const int SMEM128 = (128 + 2 * 128) * 132 * 4;
    const int SMEM64  = (128 + 2 * 64) * 132 * 4;
    cudaFuncSetAttribute((const void*)mma_gemm_kernel<128, 0, false>,
                         cudaFuncAttributeMaxDynamicSharedMemorySize, SMEM128);
    cudaFuncSetAttribute((const void*)mma_gemm_kernel<128, 0, true>,
                         cudaFuncAttributeMaxDynamicSharedMemorySize, SMEM128);
    cudaFuncSetAttribute((const void*)mma_gemm_kernel<64, 1, true>,
                         cudaFuncAttributeMaxDynamicSharedMemorySize, SMEM64);

    cudaStream_t s2;
    cudaStreamCreateWithFlags(&s2, cudaStreamNonBlocking);
    cudaEvent_t evF, evD, evJ, eG0[3], eG1[3], eA[3], eB[3];
    cudaEventCreateWithFlags(&evF, cudaEventDisableTiming);
    cudaEventCreateWithFlags(&evD, cudaEventDisableTiming);
    cudaEventCreateWithFlags(&evJ, cudaEventDisableTiming);
    for (int i = 0; i < 3; i++) {
        cudaEventCreateWithFlags(&eG0[i], cudaEventDisableTiming);
        cudaEventCreateWithFlags(&eG1[i], cudaEventDisableTiming);
        cudaEventCreateWithFlags(&eA[i], cudaEventDisableTiming);
        cudaEventCreateWithFlags(&eB[i], cudaEventDisableTiming);
    }

    // ---- fork: CSR build on side stream ----
    cudaEventRecord(evF, 0);
    cudaStreamWaitEvent(s2, evF, 0);
    cudaMemsetAsync(cnt, 0, NN * sizeof(int), s2);
    count_kernel<<<(NE + 255) / 256, 256, 0, s2>>>(dst);
    scan1_kernel<<<NBLK, SCAN_B, 0, s2>>>();
    cudaEventRecord(evD, s2);
    scan23_kernel<<<(NN + 255) / 256, 256, 0, s2>>>();
    fill_kernel<<<(NE + 255) / 256, 256, 0, s2>>>(src, dst);
    cudaEventRecord(evJ, s2);

    // main: weight split, then gemm1 (needs dinv only)
    const int WTOT = 3 * D * D + DOUT * D;
    wsplit_all_kernel<<<(WTOT + 255) / 256, 256>>>(W1, W2, W3, Wfc);

    const int gemmBlocksFull = (NN + 127) / 128;          // 391
    const int gb0 = NH0 / 128;                            // 196
    const int gb1 = (NN - NH0 + 127) / 128;               // 195
    const int M1 = NN - NH0;                              // 24912
    const int gatherB0 = (NH0 * 32 + 255) / 256;          // 3136
    const int gatherB1 = ((NN - NH0) * 32 + 255) / 256;   // 3114
    const float* bs[3] = {b1, b2, b3};

    cudaStreamWaitEvent(0, evD, 0);
    mma_gemm_kernel<128, 0, false><<<gemmBlocksFull, 256, SMEM128>>>(
        x, whi + 0 * D * D, wlo + 0 * D * D, nullptr, dinv, t0, NN);

    cudaStreamWaitEvent(0, evJ, 0);   // gathers need full CSR

    for (int l = 0; l < 3; l++) {
        const __half* tin = (l & 1) ? t1 : t0;
        __half* tout      = (l & 1) ? t0 : t1;

        gather_kernel<<<gatherB0, 256>>>(tin, bs[l], h, 0, NH0);
        cudaEventRecord(eG0[l], 0);
        gather_kernel<<<gatherB1, 256>>>(tin, bs[l], h, NH0, NN);
        cudaEventRecord(eG1[l], 0);

        if (l < 2) {
            const float* bh = whi + (l + 1) * D * D;
            const float* bl = wlo + (l + 1) * D * D;
            cudaStreamWaitEvent(s2, eG0[l], 0);
            mma_gemm_kernel<128, 0, true><<<gb0, 256, SMEM128, s2>>>(
                h, bh, bl, nullptr, dinv, tout, NH0);
            cudaEventRecord(eA[l], s2);
            cudaStreamWaitEvent(s2, eG1[l], 0);
            mma_gemm_kernel<128, 0, true><<<gb1, 256, SMEM128, s2>>>(
                h + (size_t)NH0 * D, bh, bl, nullptr, dinv + NH0,
                tout + (size_t)NH0 * D, M1);
            cudaEventRecord(eB[l], s2);
            cudaStreamWaitEvent(0, eA[l], 0);
            cudaStreamWaitEvent(0, eB[l], 0);
        } else {
            cudaStreamWaitEvent(s2, eG0[l], 0);
            mma_gemm_kernel<64, 1, true><<<gb0, 256, SMEM64, s2>>>(
                h, fhi, flo, bfc, nullptr, out, NH0);
            cudaEventRecord(eA[l], s2);
            cudaStreamWaitEvent(s2, eG1[l], 0);
            mma_gemm_kernel<64, 1, true><<<gb1, 256, SMEM64, s2>>>(
                h + (size_t)NH0 * D, fhi, flo, bfc, nullptr,
                out + (size_t)NH0 * DOUT, M1);
            cudaEventRecord(eB[l], s2);
            cudaStreamWaitEvent(0, eA[l], 0);
            cudaStreamWaitEvent(0, eB[l], 0);
        }
    }

    cudaEventDestroy(evF);
    cudaEventDestroy(evD);
    cudaEventDestroy(evJ);
    for (int i = 0; i < 3; i++) {
        cudaEventDestroy(eG0[i]);
        cudaEventDestroy(eG1[i]);
        cudaEventDestroy(eA[i]);
        cudaEventDestroy(eB[i]);
    }
    cudaStreamDestroy(s2);
}

// round 10
// speedup vs baseline: 1.1729x; 1.1729x over previous
#include <cuda_runtime.h>
#include <cuda_fp16.h>
#include <cstdint>

#define NN 50000
#define NE 800000
#define D 128
#define DOUT 64
#define SCAN_B 512
#define NBLK ((NN + SCAN_B - 1) / SCAN_B)   // 98

// ---- scratch (__device__ globals: allocation-free rule) ----
__device__ int    g_cnt[NN];
__device__ int    g_fill[NN];
__device__ int    g_rowptr[NN + 1];
__device__ float  g_dinv[NN];
__device__ int    g_blksum[NBLK];
__device__ int    g_ecol[NE];
__device__ __half g_t[NN * D];         // messages (dinv-scaled hW, fp16)
__device__ __half g_h[NN * D];         // layer features (fp16)
__device__ float  g_wt_hi[3][D * D];
__device__ float  g_wt_lo[3][D * D];
__device__ float  g_wfc_hi[DOUT * D];
__device__ float  g_wfc_lo[DOUT * D];

// ================= helpers =================
__device__ __forceinline__ float tf32rn(float x) {
    uint32_t r;
    asm("cvt.rna.tf32.f32 %0, %1;" : "=r"(r) : "f"(x));
    return __uint_as_float(r);
}
__device__ __forceinline__ void split_tf32(float x, uint32_t& hi, uint32_t& lo) {
    asm("cvt.rna.tf32.f32 %0, %1;" : "=r"(hi) : "f"(x));
    float r = x - __uint_as_float(hi);
    asm("cvt.rna.tf32.f32 %0, %1;" : "=r"(lo) : "f"(r));
}
__device__ __forceinline__ void mma_tf32(float* c, const uint32_t* a, const uint32_t* b) {
    asm volatile(
        "mma.sync.aligned.m16n8k8.row.col.f32.tf32.tf32.f32 "
        "{%0,%1,%2,%3}, {%4,%5,%6,%7}, {%8,%9}, {%0,%1,%2,%3};"
        : "+f"(c[0]), "+f"(c[1]), "+f"(c[2]), "+f"(c[3])
        : "r"(a[0]), "r"(a[1]), "r"(a[2]), "r"(a[3]), "r"(b[0]), "r"(b[1]));
}

// ================= CSR build =================
__global__ void count_kernel(const int* __restrict__ dst) {
    int e = blockIdx.x * blockDim.x + threadIdx.x;
    if (e < NE) atomicAdd(&g_cnt[dst[e]], 1);
}

__global__ void scan1_kernel() {
    __shared__ int wsum[16];
    int t = threadIdx.x;
    int i = blockIdx.x * SCAN_B + t;
    int v = (i < NN) ? g_cnt[i] : 0;
    if (i < NN) g_dinv[i] = rsqrtf((float)v + 1.0f);
    int lane = t & 31, w = t >> 5;
    int s = v;
    #pragma unroll
    for (int off = 1; off < 32; off <<= 1) {
        int x = __shfl_up_sync(0xFFFFFFFF, s, off);
        if (lane >= off) s += x;
    }
    if (lane == 31) wsum[w] = s;
    __syncthreads();
    if (w == 0) {
        int ws = (lane < 16) ? wsum[lane] : 0;
        #pragma unroll
        for (int off = 1; off < 16; off <<= 1) {
            int x = __shfl_up_sync(0xFFFFFFFF, ws, off);
            if (lane >= off) ws += x;
        }
        if (lane < 16) wsum[lane] = ws;
    }
    __syncthreads();
    if (w > 0) s += wsum[w - 1];
    if (i < NN) g_rowptr[i + 1] = s;
    if (t == SCAN_B - 1) g_blksum[blockIdx.x] = s;
}

__global__ void scan23_kernel() {
    __shared__ int s[128];
    int t = threadIdx.x;
    if (t < 128) s[t] = (t < NBLK) ? g_blksum[t] : 0;
    __syncthreads();
    #pragma unroll
    for (int off = 1; off < 128; off <<= 1) {
        int x = (t >= off && t < 128) ? s[t - off] : 0;
        __syncthreads();
        if (t < 128) s[t] += x;
        __syncthreads();
    }
    int i = blockIdx.x * 256 + t;
    if (i < NN) {
        int blk = i / SCAN_B;
        int off = (blk > 0) ? s[blk - 1] : 0;
        g_rowptr[i + 1] += off;
        g_fill[i] = 0;
    }
    if (i == 0) g_rowptr[0] = 0;
}

__global__ void fill_kernel(const int* __restrict__ src,
                            const int* __restrict__ dst) {
    int e = blockIdx.x * blockDim.x + threadIdx.x;
    if (e >= NE) return;
    int d = dst[e];
    int pos = g_rowptr[d] + atomicAdd(&g_fill[d], 1);
    g_ecol[pos] = src[e];
}

// ===== all-weight transpose + tf32 hi/lo split =====
__global__ void wsplit_all_kernel(const float* __restrict__ W1,
                                  const float* __restrict__ W2,
                                  const float* __restrict__ W3,
                                  const float* __restrict__ Wfc) {
    int idx = blockIdx.x * blockDim.x + threadIdx.x;
    const int SQ = D * D;
    const float* W;
    float *hi, *lo;
    int ncols, local;
    if (idx < SQ)          { W = W1;  hi = g_wt_hi[0]; lo = g_wt_lo[0]; ncols = D;    local = idx; }
    else if (idx < 2 * SQ) { W = W2;  hi = g_wt_hi[1]; lo = g_wt_lo[1]; ncols = D;    local = idx - SQ; }
    else if (idx < 3 * SQ) { W = W3;  hi = g_wt_hi[2]; lo = g_wt_lo[2]; ncols = D;    local = idx - 2 * SQ; }
    else if (idx < 3 * SQ + DOUT * D)
                           { W = Wfc; hi = g_wfc_hi;   lo = g_wfc_lo;   ncols = DOUT; local = idx - 3 * SQ; }
    else return;
    int n = local / D, k = local % D;
    float w = W[k * ncols + n];
    float h_ = tf32rn(w);
    hi[local] = h_;
    lo[local] = tf32rn(w - h_);
}

// ===== mma.sync tf32 GEMM: C[M,BN] = A[M,128] @ (Bhi+Blo)^T, 3-term split =====
// AHALF: A rows fp16.  EPI 0: half2 C[r,:] = acc*dinv[r]; EPI 1: float C = acc+bias.
template<int BN, int EPI, bool AHALF>
__global__ void __launch_bounds__(256, 1)
mma_gemm_kernel(const void* __restrict__ Ain,
                const float* __restrict__ Bhi,
                const float* __restrict__ Blo,
                const float* __restrict__ bias,
                void* __restrict__ Cout, int M) {
    constexpr int TN_W = BN / 2;
    constexpr int NT = TN_W / 8;
    constexpr int LDS = 132;
    extern __shared__ float s[];
    float* As = s;
    float* Bh = s + 128 * LDS;
    float* Bl = Bh + BN * LDS;

    const int tid = threadIdx.x;
    const int lane = tid & 31, warp = tid >> 5;
    const int warpM = warp & 3, warpN = warp >> 2;
    const int rowBlk = blockIdx.x * 128;
    const int g = lane >> 2, tig = lane & 3;

    if (AHALF) {
        const __half* Ah = (const __half*)Ain;
        // 128 rows x 16 uint4/row = 2048 items = 8 iterations of 256 threads
        #pragma unroll
        for (int i = 0; i < 8; i++) {
            int idx = i * 256 + tid;
            int r = idx >> 4, c8 = idx & 15;
            float4 lo4 = make_float4(0.f, 0.f, 0.f, 0.f);
            float4 hi4 = make_float4(0.f, 0.f, 0.f, 0.f);
            if (rowBlk + r < M) {
                uint4 u = ((const uint4*)(Ah + (size_t)(rowBlk + r) * D))[c8];
                float2 f0 = __half22float2(*(__half2*)&u.x);
                float2 f1 = __half22float2(*(__half2*)&u.y);
                float2 f2 = __half22float2(*(__half2*)&u.z);
                float2 f3 = __half22float2(*(__half2*)&u.w);
                lo4 = make_float4(f0.x, f0.y, f1.x, f1.y);
                hi4 = make_float4(f2.x, f2.y, f3.x, f3.y);
            }
            *(float4*)(As + r * LDS + c8 * 8)     = lo4;
            *(float4*)(As + r * LDS + c8 * 8 + 4) = hi4;
        }
    } else {
        const float* Af = (const float*)Ain;
        #pragma unroll
        for (int i = 0; i < 16; i++) {
            int idx = i * 256 + tid;
            int r = idx >> 5, c4 = idx & 31;
            float4 v = make_float4(0.f, 0.f, 0.f, 0.f);
            if (rowBlk + r < M) v = ((const float4*)Af)[(size_t)(rowBlk + r) * 32 + c4];
            *(float4*)(As + r * LDS + c4 * 4) = v;
        }
    }
    #pragma unroll
    for (int i = 0; i < BN / 8; i++) {
        int idx = i * 256 + tid;
        int r = idx >> 5, c4 = idx & 31;
        *(float4*)(Bh + r * LDS + c4 * 4) = ((const float4*)Bhi)[(size_t)r * 32 + c4];
        *(float4*)(Bl + r * LDS + c4 * 4) = ((const float4*)Blo)[(size_t)r * 32 + c4];
    }
    __syncthreads();

    float acc[2][NT][4];
    #pragma unroll
    for (int mt = 0; mt < 2; mt++)
        #pragma unroll
        for (int nt = 0; nt < NT; nt++)
            #pragma unroll
            for (int q = 0; q < 4; q++) acc[mt][nt][q] = 0.f;

    const int aBase = warpM * 32;
    const int nBase = warpN * TN_W;

    #pragma unroll 4
    for (int ks = 0; ks < 16; ks++) {
        const int k0 = ks * 8;
        uint32_t ahi[2][4], alo[2][4];
        #pragma unroll
        for (int mt = 0; mt < 2; mt++) {
            int r0 = aBase + mt * 16 + g;
            float a0 = As[r0 * LDS + k0 + tig];
            float a1 = As[(r0 + 8) * LDS + k0 + tig];
            float a2 = As[r0 * LDS + k0 + tig + 4];
            float a3 = As[(r0 + 8) * LDS + k0 + tig + 4];
            split_tf32(a0, ahi[mt][0], alo[mt][0]);
            split_tf32(a1, ahi[mt][1], alo[mt][1]);
            split_tf32(a2, ahi[mt][2], alo[mt][2]);
            split_tf32(a3, ahi[mt][3], alo[mt][3]);
        }
        uint32_t bhi[NT][2], blo[NT][2];
        #pragma unroll
        for (int nt = 0; nt < NT; nt++) {
            int n = nBase + nt * 8 + g;
            bhi[nt][0] = __float_as_uint(Bh[n * LDS + k0 + tig]);
            bhi[nt][1] = __float_as_uint(Bh[n * LDS + k0 + tig + 4]);
            blo[nt][0] = __float_as_uint(Bl[n * LDS + k0 + tig]);
            blo[nt][1] = __float_as_uint(Bl[n * LDS + k0 + tig + 4]);
        }
        #pragma unroll
        for (int mt = 0; mt < 2; mt++)
            #pragma unroll
            for (int nt = 0; nt < NT; nt++)
                mma_tf32(acc[mt][nt], ahi[mt], bhi[nt]);
        #pragma unroll
        for (int mt = 0; mt < 2; mt++)
            #pragma unroll
            for (int nt = 0; nt < NT; nt++)
                mma_tf32(acc[mt][nt], alo[mt], bhi[nt]);
        #pragma unroll
        for (int mt = 0; mt < 2; mt++)
            #pragma unroll
            for (int nt = 0; nt < NT; nt++)
                mma_tf32(acc[mt][nt], ahi[mt], blo[nt]);
    }

    #pragma unroll
    for (int mt = 0; mt < 2; mt++) {
        int r0 = rowBlk + aBase + mt * 16 + g;
        int r1 = r0 + 8;
        float s0 = 1.f, s1 = 1.f;
        if (EPI == 0) {
            if (r0 < M) s0 = g_dinv[r0];
            if (r1 < M) s1 = g_dinv[r1];
        }
        #pragma unroll
        for (int nt = 0; nt < NT; nt++) {
            int cn = nBase + nt * 8 + 2 * tig;
            float2 v0 = make_float2(acc[mt][nt][0], acc[mt][nt][1]);
            float2 v1 = make_float2(acc[mt][nt][2], acc[mt][nt][3]);
            if (EPI == 0) {
                v0.x *= s0; v0.y *= s0; v1.x *= s1; v1.y *= s1;
                __half* Ch = (__half*)Cout;
                if (r0 < M) *(__half2*)(Ch + (size_t)r0 * BN + cn) = __float22half2_rn(v0);
                if (r1 < M) *(__half2*)(Ch + (size_t)r1 * BN + cn) = __float22half2_rn(v1);
            } else {
                float b0 = bias[cn], b1 = bias[cn + 1];
                v0.x += b0; v0.y += b1; v1.x += b0; v1.y += b1;
                float* Cf = (float*)Cout;
                if (r0 < M) *(float2*)(Cf + (size_t)r0 * BN + cn) = v0;
                if (r1 < M) *(float2*)(Cf + (size_t)r1 * BN + cn) = v1;
            }
        }
    }
}

// ========= gather: warp per node, fp16 in, fp16 out, fp32 accumulate, MLP=8 =========
__device__ __forceinline__ float4 ldrow_h(const uint2* __restrict__ t2, int row, int lane) {
    uint2 u = __ldg(t2 + (size_t)row * 32 + lane);
    float2 fa = __half22float2(*(__half2*)&u.x);
    float2 fb = __half22float2(*(__half2*)&u.y);
    return make_float4(fa.x, fa.y, fb.x, fb.y);
}

__global__ void gather_kernel(const __half* __restrict__ tin,
                              const float* __restrict__ bias,
                              __half* __restrict__ hout) {
    int node = (blockIdx.x * blockDim.x + threadIdx.x) >> 5;
    int lane = threadIdx.x & 31;
    if (node >= NN) return;
    const uint2* t2 = (const uint2*)tin;

    float4 acc = ldrow_h(t2, node, lane);   // self term (pre-scaled)
    int e = g_rowptr[node], end = g_rowptr[node + 1];
    for (; e + 8 <= end; e += 8) {
        int sc[8];
        #pragma unroll
        for (int j = 0; j < 8; j++) sc[j] = g_ecol[e + j];
        float4 v[8];
        #pragma unroll
        for (int j = 0; j < 8; j++) v[j] = ldrow_h(t2, sc[j], lane);
        #pragma unroll
        for (int j = 0; j < 8; j++) {
            acc.x += v[j].x; acc.y += v[j].y; acc.z += v[j].z; acc.w += v[j].w;
        }
    }
    if (e + 4 <= end) {
        int sc[4];
        #pragma unroll
        for (int j = 0; j < 4; j++) sc[j] = g_ecol[e + j];
        float4 v[4];
        #pragma unroll
        for (int j = 0; j < 4; j++) v[j] = ldrow_h(t2, sc[j], lane);
        #pragma unroll
        for (int j = 0; j < 4; j++) {
            acc.x += v[j].x; acc.y += v[j].y; acc.z += v[j].z; acc.w += v[j].w;
        }
        e += 4;
    }
    for (; e < end; e++) {
        float4 v = ldrow_h(t2, g_ecol[e], lane);
        acc.x += v.x; acc.y += v.y; acc.z += v.z; acc.w += v.w;
    }
    float dd = g_dinv[node];
    float4 b = ((const float4*)bias)[lane];
    float2 p0 = make_float2(fmaxf(fmaf(dd, acc.x, b.x), 0.0f),
                            fmaxf(fmaf(dd, acc.y, b.y), 0.0f));
    float2 p1 = make_float2(fmaxf(fmaf(dd, acc.z, b.z), 0.0f),
                            fmaxf(fmaf(dd, acc.w, b.w), 0.0f));
    uint2 o;
    *(__half2*)&o.x = __float22half2_rn(p0);
    *(__half2*)&o.y = __float22half2_rn(p1);
    ((uint2*)hout)[(size_t)node * 32 + lane] = o;
}

// ================= launch =================
extern "C" void kernel_launch(void* const* d_in, const int* in_sizes, int n_in,
                              void* d_out, int out_size) {
    const float* x   = (const float*)d_in[0];
    const int* eidx  = (const int*)d_in[1];
    const float* W1  = (const float*)d_in[2];
    const float* b1  = (const float*)d_in[3];
    const float* W2  = (const float*)d_in[4];
    const float* b2  = (const float*)d_in[5];
    const float* W3  = (const float*)d_in[6];
    const float* b3  = (const float*)d_in[7];
    const float* Wfc = (const float*)d_in[8];
    const float* bfc = (const float*)d_in[9];
    float* out = (float*)d_out;

    const int* src = eidx;
    const int* dst = eidx + NE;

    __half* t; cudaGetSymbolAddress((void**)&t, g_t);
    __half* h; cudaGetSymbolAddress((void**)&h, g_h);
    int* cnt;  cudaGetSymbolAddress((void**)&cnt, g_cnt);
    float* whi; cudaGetSymbolAddress((void**)&whi, g_wt_hi);
    float* wlo; cudaGetSymbolAddress((void**)&wlo, g_wt_lo);
    float* fhi; cudaGetSymbolAddress((void**)&fhi, g_wfc_hi);
    float* flo; cudaGetSymbolAddress((void**)&flo, g_wfc_lo);

    const int SMEM128 = (128 + 2 * 128) * 132 * 4;
    const int SMEM64  = (128 + 2 * 64) * 132 * 4;
    cudaFuncSetAttribute((const void*)mma_gemm_kernel<128, 0, false>,
                         cudaFuncAttributeMaxDynamicSharedMemorySize, SMEM128);
    cudaFuncSetAttribute((const void*)mma_gemm_kernel<128, 0, true>,
                         cudaFuncAttributeMaxDynamicSharedMemorySize, SMEM128);
    cudaFuncSetAttribute((const void*)mma_gemm_kernel<64, 1, true>,
                         cudaFuncAttributeMaxDynamicSharedMemorySize, SMEM64);

    // ---- fork: CSR build on side stream ----
    cudaStream_t s2;
    cudaStreamCreateWithFlags(&s2, cudaStreamNonBlocking);
    cudaEvent_t evF, evD, evJ;
    cudaEventCreateWithFlags(&evF, cudaEventDisableTiming);
    cudaEventCreateWithFlags(&evD, cudaEventDisableTiming);
    cudaEventCreateWithFlags(&evJ, cudaEventDisableTiming);

    cudaEventRecord(evF, 0);
    cudaStreamWaitEvent(s2, evF, 0);
    cudaMemsetAsync(cnt, 0, NN * sizeof(int), s2);
    count_kernel<<<(NE + 255) / 256, 256, 0, s2>>>(dst);
    scan1_kernel<<<NBLK, SCAN_B, 0, s2>>>();
    cudaEventRecord(evD, s2);                       // dinv ready
    scan23_kernel<<<(NN + 255) / 256, 256, 0, s2>>>();
    fill_kernel<<<(NE + 255) / 256, 256, 0, s2>>>(src, dst);
    cudaEventRecord(evJ, s2);                       // CSR ready

    // main: weight split (independent), then gemm1 (needs dinv only)
    const int WTOT = 3 * D * D + DOUT * D;
    wsplit_all_kernel<<<(WTOT + 255) / 256, 256>>>(W1, W2, W3, Wfc);

    const int gemmBlocks = (NN + 127) / 128;
    const int gatherBlocks = (NN * 32 + 255) / 256;
    const float* bs[3] = {b1, b2, b3};

    cudaStreamWaitEvent(0, evD, 0);
    mma_gemm_kernel<128, 0, false><<<gemmBlocks, 256, SMEM128>>>(
        x, whi + 0 * D * D, wlo + 0 * D * D, nullptr, t, NN);

    cudaStreamWaitEvent(0, evJ, 0);   // join: gather needs full CSR

    for (int l = 0; l < 3; l++) {
        gather_kernel<<<gatherBlocks, 256>>>(t, bs[l], h);
        if (l < 2) {
            mma_gemm_kernel<128, 0, true><<<gemmBlocks, 256, SMEM128>>>(
                h, whi + (l + 1) * D * D, wlo + (l + 1) * D * D, nullptr, t, NN);
        }
    }
    mma_gemm_kernel<64, 1, true><<<gemmBlocks, 256, SMEM64>>>(h, fhi, flo, bfc, out, NN);

    cudaEventDestroy(evF);
    cudaEventDestroy(evD);
    cudaEventDestroy(evJ);
    cudaStreamDestroy(s2);
}